// round 10
// baseline (speedup 1.0000x reference)
#include <cuda_runtime.h>
#include <cuda_bf16.h>
#include <mma.h>
#include <math.h>

using namespace nvcuda;

#define Ln 8
#define Tn 512
#define Hn 128
#define Bn 64
#define G4 512
#define Vn 65
#define On 65
#define CPL 16
#define NTHR 256
#define LDA 264          // padded k-stride (elements)
#define LDG 36           // padded gate-row stride (floats)
#define OUT_MAIN (Bn*Tn*On)
#define OUT_H_BASE OUT_MAIN
#define OUT_C_BASE (OUT_MAIN + Ln*Bn*Hn)

// SMEM layout (bytes)
#define SM_GSM   0                        // 64*36*4 = 9216
#define SM_BIAS  9216                     // 128
#define SM_WHI   9344                     // 32*264*2 = 16896
#define SM_WLO   (SM_WHI + 16896)
#define SM_A     (SM_WLO + 16896)         // Abuf[2][2][33792]
#define SM_ASZ   33792                    // 64*264*2
#define SM_TOTAL (SM_A + 4*SM_ASZ)        // 178304

__device__ __align__(16) __nv_bfloat16 g_hh[2][(size_t)Ln*Tn*Bn*Hn]; // [arr][l][t][b][u]
__device__ __align__(16) __nv_bfloat16 g_emb[2][Vn*Hn];
__device__ __align__(16) __nv_bfloat16 g_W[2][Ln*CPL*32*256];        // [arr][l][gidx][n][k]
__device__ float    g_bias[Ln*G4];
__device__ float    g_h7[(size_t)Tn*Hn*Bn];                          // [t][u][b]
__device__ int      g_xT[Tn*Bn];
__device__ unsigned g_flag[Ln*CPL];                                  // monotonic: beat t done -> t+1

__device__ __forceinline__ unsigned ld_acq(const unsigned* p){
    unsigned v; asm volatile("ld.acquire.gpu.global.u32 %0, [%1];" : "=r"(v) : "l"(p) : "memory"); return v;
}
__device__ __forceinline__ void st_rel(unsigned* p, unsigned v){
    asm volatile("st.release.gpu.global.u32 [%0], %1;" :: "l"(p), "r"(v) : "memory");
}
__device__ __forceinline__ float fsig(float x){ return __fdividef(1.f, 1.f + __expf(-x)); }
__device__ __forceinline__ float ftanh(float x){ return 1.f - __fdividef(2.f, __expf(2.f*x)+1.f); }
__device__ __forceinline__ unsigned smaddr(const void* p){
    unsigned a; asm("{ .reg .u64 t; cvta.to.shared.u64 t, %1; cvt.u32.u64 %0, t; }" : "=r"(a) : "l"(p)); return a;
}
__device__ __forceinline__ void cpa16(unsigned dst, const void* src){
    asm volatile("cp.async.cg.shared.global [%0], [%1], 16;" :: "r"(dst), "l"(src) : "memory");
}
__device__ __forceinline__ void cpa_fence(){
    asm volatile("cp.async.commit_group;" ::: "memory");
    asm volatile("cp.async.wait_group 0;" ::: "memory");
}
__device__ __forceinline__ void sts_zero16(unsigned dst){
    asm volatile("st.shared.v4.b32 [%0], {%1,%1,%1,%1};" :: "r"(dst), "r"(0u) : "memory");
}

// ---------------------------------------------------------------------------
__global__ void k_reset(const int* __restrict__ x){
    int i = blockIdx.x*blockDim.x + threadIdx.x;
    if (i < Ln*CPL) g_flag[i] = 0u;
    if (i < Tn*Bn){ int t = i/Bn, b = i%Bn; g_xT[i] = x[b*Tn + t]; }
}

__global__ void k_prep_w(const float* __restrict__ w_ih, const float* __restrict__ w_hh,
                         const float* __restrict__ b_ih, const float* __restrict__ b_hh){
    int gid = blockIdx.x*256 + threadIdx.x;
    if (gid >= Ln*G4*256) return;
    int k = gid & 255, col = (gid>>8)&511, l = gid>>17;
    int gate = col>>7, u = col&127, gidx = u>>3, ul = u&7, n = ul*4+gate;
    float w = (k < Hn) ? w_ih[(l*Hn+k)*G4+col] : w_hh[(l*Hn+k-Hn)*G4+col];
    __nv_bfloat16 hi = __float2bfloat16_rn(w);
    int idx = ((l*CPL+gidx)*32 + n)*256 + k;
    g_W[0][idx] = hi;
    g_W[1][idx] = __float2bfloat16_rn(w - __bfloat162float(hi));
    if (k == 0) g_bias[l*G4 + gidx*32 + n] = b_ih[l*G4+col] + b_hh[l*G4+col];
}

__global__ void k_prep_e(const float* __restrict__ embed){
    int i = blockIdx.x*256 + threadIdx.x;
    if (i < Vn*Hn){
        float e = embed[i];
        __nv_bfloat16 hi = __float2bfloat16_rn(e);
        g_emb[0][i] = hi;
        g_emb[1][i] = __float2bfloat16_rn(e - __bfloat162float(hi));
    }
}

// ---------------------------------------------------------------------------
// Persistent wavefront LSTM; wmma bf16 3-term; atomic-free per-CTA release flags.
__global__ void __launch_bounds__(NTHR, 1) k_lstm(float* __restrict__ out)
{
    extern __shared__ char smraw[];
    float* Gsm = (float*)(smraw + SM_GSM);
    float* Bsm = (float*)(smraw + SM_BIAS);
    __nv_bfloat16* Whi = (__nv_bfloat16*)(smraw + SM_WHI);
    __nv_bfloat16* Wlo = (__nv_bfloat16*)(smraw + SM_WLO);
    const unsigned sWhi = smaddr(Whi), sWlo = smaddr(Wlo);
    const unsigned sA   = smaddr(smraw + SM_A);

    const int layer = blockIdx.x >> 4;
    const int gidx  = blockIdx.x & 15;
    const int tid   = threadIdx.x;
    const int wid   = tid >> 5;
    const int lane  = tid & 31;

    if (tid < 32) Bsm[tid] = g_bias[layer*G4 + gidx*32 + tid];

    // stage W once
    {
        const char* ws[2] = { (const char*)&g_W[0][((layer*CPL+gidx)*32)*256],
                              (const char*)&g_W[1][((layer*CPL+gidx)*32)*256] };
#pragma unroll
        for (int j = 0; j < 8; ++j){
            int id = j*NTHR + tid, arr = id>>10, rem = id&1023;
            int n = rem>>5, k0 = (rem&31)*8;
            cpa16((arr ? sWlo : sWhi) + (unsigned)(n*LDA + k0)*2u, ws[arr] + (n*256 + k0)*2);
        }
        cpa_fence();
    }
    __syncthreads();

    const int r16 = (wid >> 1) * 16;
    const int c16 = (wid & 1)  * 16;
    const int cb  = r16 + (lane >> 1);
    const int cs  = lane & 1;
    const int ug0 = gidx*8 + (wid & 1)*4 + cs*2;

    float bia[8];
#pragma unroll
    for (int j = 0; j < 8; ++j) bia[j] = Bsm[c16 + cs*8 + j];

    float cst0 = 0.f, cst1 = 0.f;

    const unsigned* fB = &g_flag[(layer-1)*CPL];   // below-layer flags (layer>0)
    const unsigned* fO = &g_flag[layer*CPL];       // own-layer flags
    unsigned* myflag = &g_flag[layer*CPL + gidx];

    for (int t = 0; t < Tn; ++t){
        // ---- parallel, atomic-free flag polls: lanes 0-15 below, 16-31 own ----
        if (lane < 16){
            if (layer > 0){
                unsigned need = (unsigned)(t + 1);
                while (ld_acq(&fB[lane]) < need) __nanosleep(8);
            }
        } else {
            if (t > 0){
                unsigned need = (unsigned)t;
                while (ld_acq(&fO[lane-16]) < need) __nanosleep(8);
            }
        }
        __syncwarp();

        // ---- stage A into buf[t&1] (hi/lo) ----
        const unsigned aBuf = sA + (unsigned)(t & 1) * (2u*SM_ASZ);
        {
            const char* h0b[2]; const char* h1b[2];
            if (layer > 0){
                h0b[0] = (const char*)&g_hh[0][((size_t)(layer-1)*Tn + t)*Bn*Hn];
                h0b[1] = (const char*)&g_hh[1][((size_t)(layer-1)*Tn + t)*Bn*Hn];
            } else { h0b[0] = (const char*)g_emb[0]; h0b[1] = (const char*)g_emb[1]; }
            if (t > 0){
                h1b[0] = (const char*)&g_hh[0][((size_t)layer*Tn + (t-1))*Bn*Hn];
                h1b[1] = (const char*)&g_hh[1][((size_t)layer*Tn + (t-1))*Bn*Hn];
            }
            const int* xr = &g_xT[t*Bn];
#pragma unroll
            for (int j = 0; j < 16; ++j){
                int id = j*NTHR + tid, arr = id>>11, rem = id&2047;
                int b = rem>>5, k0 = (rem&31)*8;
                unsigned dst = aBuf + (unsigned)arr*SM_ASZ + (unsigned)(b*LDA + k0)*2u;
                if (k0 < 128){
                    const char* s = (layer==0) ? h0b[arr] + (xr[b]*Hn + k0)*2
                                               : h0b[arr] + (b*Hn + k0)*2;
                    cpa16(dst, s);
                } else if (t > 0){
                    cpa16(dst, h1b[arr] + (b*Hn + k0 - 128)*2);
                } else {
                    sts_zero16(dst);
                }
            }
            cpa_fence();
        }
        __syncthreads();   // all staging visible to all MMA warps

        // ---- tensor GEMM (3-term hi/lo) ----
        const __nv_bfloat16* Ahi = (const __nv_bfloat16*)(smraw + SM_A + (t&1)*(2*SM_ASZ));
        const __nv_bfloat16* Alo = (const __nv_bfloat16*)(smraw + SM_A + (t&1)*(2*SM_ASZ) + SM_ASZ);
        {
            wmma::fragment<wmma::accumulator, 16,16,16, float> acc;
            wmma::fill_fragment(acc, 0.0f);
#pragma unroll
            for (int ks = 0; ks < 16; ++ks){
                wmma::fragment<wmma::matrix_a, 16,16,16, __nv_bfloat16, wmma::row_major> ah, al;
                wmma::fragment<wmma::matrix_b, 16,16,16, __nv_bfloat16, wmma::col_major> bh, bl;
                wmma::load_matrix_sync(ah, Ahi + r16*LDA + ks*16, LDA);
                wmma::load_matrix_sync(al, Alo + r16*LDA + ks*16, LDA);
                wmma::load_matrix_sync(bh, Whi + c16*LDA + ks*16, LDA);
                wmma::load_matrix_sync(bl, Wlo + c16*LDA + ks*16, LDA);
                wmma::mma_sync(acc, ah, bh, acc);
                wmma::mma_sync(acc, ah, bl, acc);
                wmma::mma_sync(acc, al, bh, acc);
            }
            wmma::store_matrix_sync(&Gsm[r16*LDG + c16], acc, LDG, wmma::mem_row_major);
        }
        __syncwarp();

        // ---- per-warp cell: 2 cells per lane ----
        {
            const float* gr = &Gsm[cb*LDG + c16 + cs*8];
            float4 gA = *(const float4*)(gr);
            float4 gB = *(const float4*)(gr + 4);
            float i0 = fsig (gA.x + bia[0]);
            float f0 = fsig (gA.y + bia[1]);
            float g0 = ftanh(gA.z + bia[2]);
            float o0 = fsig (gA.w + bia[3]);
            float i1 = fsig (gB.x + bia[4]);
            float f1 = fsig (gB.y + bia[5]);
            float g1 = ftanh(gB.z + bia[6]);
            float o1 = fsig (gB.w + bia[7]);
            cst0 = f0*cst0 + i0*g0;
            cst1 = f1*cst1 + i1*g1;
            float h0 = o0 * ftanh(cst0);
            float h1 = o1 * ftanh(cst1);

            __nv_bfloat16 bh0 = __float2bfloat16_rn(h0);
            __nv_bfloat16 bh1 = __float2bfloat16_rn(h1);
            __nv_bfloat16 bl0 = __float2bfloat16_rn(h0 - __bfloat162float(bh0));
            __nv_bfloat16 bl1 = __float2bfloat16_rn(h1 - __bfloat162float(bh1));
            unsigned hp = ((unsigned)__bfloat16_as_ushort(bh1)<<16) | __bfloat16_as_ushort(bh0);
            unsigned lp = ((unsigned)__bfloat16_as_ushort(bl1)<<16) | __bfloat16_as_ushort(bl0);

            size_t ho = (((size_t)layer*Tn + t)*Bn + cb)*Hn + ug0;
            *(unsigned*)&g_hh[0][ho] = hp;
            *(unsigned*)&g_hh[1][ho] = lp;
            if (layer == 7){
                g_h7[((size_t)t*Hn + ug0    )*Bn + cb] = h0;
                g_h7[((size_t)t*Hn + ug0 + 1)*Bn + cb] = h1;
            }
            if (t == Tn-1){
                *(float2*)&out[OUT_H_BASE + (layer*Bn + cb)*Hn + ug0] = make_float2(h0, h1);
                *(float2*)&out[OUT_C_BASE + (layer*Bn + cb)*Hn + ug0] = make_float2(cst0, cst1);
            }
        }

        // ---- atomic-free release: one store per CTA ----
        __syncthreads();                 // all warps' h-stores issued (happens-before tid0)
        if (tid == 0){
            __threadfence();             // cumulative: makes all CTA stores GPU-visible
            st_rel(myflag, (unsigned)(t + 1));
        }
    }
}

// ---------------------------------------------------------------------------
__global__ void k_out(const float* __restrict__ w_out, const float* __restrict__ b_out,
                      float* __restrict__ out){
    extern __shared__ float sm[];
    float* Hs = sm;            // [128][64]
    float* Ws = sm + 8192;     // [128][65]
    int t = blockIdx.x, tid = threadIdx.x;
    const float4* s = (const float4*)&g_h7[(size_t)t*Hn*Bn];
    for (int i = tid; i < 2048; i += 256) ((float4*)Hs)[i] = s[i];
    for (int i = tid; i < Hn*On; i += 256) Ws[i] = w_out[i];
    __syncthreads();
    int b = tid & 63, og = tid >> 6;
    for (int o = og; o < On; o += 4){
        float acc = b_out[o];
#pragma unroll 8
        for (int k = 0; k < Hn; ++k) acc += Hs[k*Bn + b] * Ws[k*On + o];
        out[(b*Tn + t)*On + o] = acc;
    }
}

// ---------------------------------------------------------------------------
extern "C" void kernel_launch(void* const* d_in, const int* in_sizes, int n_in,
                              void* d_out, int out_size)
{
    const int*   x     = (const int*)  d_in[0];
    const float* embed = (const float*)d_in[1];
    const float* w_ih  = (const float*)d_in[2];
    const float* b_ih  = (const float*)d_in[3];
    const float* w_hh  = (const float*)d_in[4];
    const float* b_hh  = (const float*)d_in[5];
    const float* w_out = (const float*)d_in[6];
    const float* b_out = (const float*)d_in[7];
    float* out = (float*)d_out;

    size_t smem_lstm = SM_TOTAL;                                   // 178,304 B
    size_t smem_out  = (size_t)(8192 + Hn*On) * sizeof(float);
    cudaFuncSetAttribute(k_lstm, cudaFuncAttributeMaxDynamicSharedMemorySize, (int)smem_lstm);
    cudaFuncSetAttribute(k_out,  cudaFuncAttributeMaxDynamicSharedMemorySize, (int)smem_out);

    k_reset<<<128, 256>>>(x);
    k_prep_w<<<(Ln*G4*256)/256, 256>>>(w_ih, w_hh, b_ih, b_hh);
    k_prep_e<<<(Vn*Hn + 255)/256, 256>>>(embed);
    k_lstm<<<Ln*CPL, NTHR, smem_lstm>>>(out);
    k_out<<<Tn, 256, smem_out>>>(w_out, b_out, out);
}

// round 12
// speedup vs baseline: 1.4998x; 1.4998x over previous
#include <cuda_runtime.h>
#include <cuda_bf16.h>
#include <mma.h>
#include <math.h>

using namespace nvcuda;

#define Ln 8
#define Tn 512
#define Hn 128
#define Bn 64
#define G4 512
#define Vn 65
#define On 65
#define CPL 16
#define NTHR 256
#define LDA 264          // padded k-stride (elements)
#define LDG 36           // padded gate-row stride (floats)
#define OUT_MAIN (Bn*Tn*On)
#define OUT_H_BASE OUT_MAIN
#define OUT_C_BASE (OUT_MAIN + Ln*Bn*Hn)

// SMEM layout (bytes)
#define SM_GSM   0                        // 64*36*4 = 9216
#define SM_BIAS  9216                     // 128
#define SM_WHI   9344                     // 32*264*2 = 16896
#define SM_WLO   (SM_WHI + 16896)
#define SM_A     (SM_WLO + 16896)         // Abuf[2][2][33792]
#define SM_ASZ   33792                    // 64*264*2
#define SM_TOTAL (SM_A + 4*SM_ASZ)        // 178304

__device__ __align__(16) __nv_bfloat16 g_hh[2][(size_t)Ln*Tn*Bn*Hn]; // [arr][l][t][b][u]
__device__ __align__(16) __nv_bfloat16 g_emb[2][Vn*Hn];
__device__ __align__(16) __nv_bfloat16 g_W[2][Ln*CPL*32*256];        // [arr][l][gidx][n][k]
__device__ float    g_bias[Ln*G4];
__device__ float    g_h7[(size_t)Tn*Hn*Bn];                          // [t][u][b]
__device__ int      g_xT[Tn*Bn];
__device__ unsigned g_cnt[Ln*Tn];                                    // arrival counters (R8 scheme)

__device__ __forceinline__ unsigned ld_acq(const unsigned* p){
    unsigned v; asm volatile("ld.acquire.gpu.global.u32 %0, [%1];" : "=r"(v) : "l"(p) : "memory"); return v;
}
__device__ __forceinline__ void red_rel_add(unsigned* p){
    asm volatile("red.release.gpu.global.add.u32 [%0], 1;" :: "l"(p) : "memory");
}
__device__ __forceinline__ float fsig(float x){ return __fdividef(1.f, 1.f + __expf(-x)); }
__device__ __forceinline__ float ftanh(float x){ return 1.f - __fdividef(2.f, __expf(2.f*x)+1.f); }
__device__ __forceinline__ unsigned smaddr(const void* p){
    unsigned a; asm("{ .reg .u64 t; cvta.to.shared.u64 t, %1; cvt.u32.u64 %0, t; }" : "=r"(a) : "l"(p)); return a;
}
__device__ __forceinline__ void cpa16(unsigned dst, const void* src){
    asm volatile("cp.async.cg.shared.global [%0], [%1], 16;" :: "r"(dst), "l"(src) : "memory");
}
__device__ __forceinline__ void cpa_fence(){
    asm volatile("cp.async.commit_group;" ::: "memory");
    asm volatile("cp.async.wait_group 0;" ::: "memory");
}
__device__ __forceinline__ void sts_zero16(unsigned dst){
    asm volatile("st.shared.v4.b32 [%0], {%1,%1,%1,%1};" :: "r"(dst), "r"(0u) : "memory");
}

// ---------------------------------------------------------------------------
__global__ void k_reset(const int* __restrict__ x){
    int i = blockIdx.x*blockDim.x + threadIdx.x;
    if (i < Ln*Tn) g_cnt[i] = 0u;
    if (i < Tn*Bn){ int t = i/Bn, b = i%Bn; g_xT[i] = x[b*Tn + t]; }
}

__global__ void k_prep_w(const float* __restrict__ w_ih, const float* __restrict__ w_hh,
                         const float* __restrict__ b_ih, const float* __restrict__ b_hh){
    int gid = blockIdx.x*256 + threadIdx.x;
    if (gid >= Ln*G4*256) return;
    int k = gid & 255, col = (gid>>8)&511, l = gid>>17;
    int gate = col>>7, u = col&127, gidx = u>>3, ul = u&7, n = ul*4+gate;
    float w = (k < Hn) ? w_ih[(l*Hn+k)*G4+col] : w_hh[(l*Hn+k-Hn)*G4+col];
    __nv_bfloat16 hi = __float2bfloat16_rn(w);
    int idx = ((l*CPL+gidx)*32 + n)*256 + k;
    g_W[0][idx] = hi;
    g_W[1][idx] = __float2bfloat16_rn(w - __bfloat162float(hi));
    if (k == 0) g_bias[l*G4 + gidx*32 + n] = b_ih[l*G4+col] + b_hh[l*G4+col];
}

__global__ void k_prep_e(const float* __restrict__ embed){
    int i = blockIdx.x*256 + threadIdx.x;
    if (i < Vn*Hn){
        float e = embed[i];
        __nv_bfloat16 hi = __float2bfloat16_rn(e);
        g_emb[0][i] = hi;
        g_emb[1][i] = __float2bfloat16_rn(e - __bfloat162float(hi));
    }
}

// ---------------------------------------------------------------------------
// Persistent wavefront LSTM; wmma bf16 3-term with 3 independent acc chains;
// R8 sync skeleton (single counter + red.release), per-warp poll + cell.
__global__ void __launch_bounds__(NTHR, 1) k_lstm(float* __restrict__ out)
{
    extern __shared__ char smraw[];
    float* Gsm = (float*)(smraw + SM_GSM);
    float* Bsm = (float*)(smraw + SM_BIAS);
    __nv_bfloat16* Whi = (__nv_bfloat16*)(smraw + SM_WHI);
    __nv_bfloat16* Wlo = (__nv_bfloat16*)(smraw + SM_WLO);
    const unsigned sWhi = smaddr(Whi), sWlo = smaddr(Wlo);
    const unsigned sA   = smaddr(smraw + SM_A);

    const int layer = blockIdx.x >> 4;
    const int gidx  = blockIdx.x & 15;
    const int tid   = threadIdx.x;
    const int wid   = tid >> 5;
    const int lane  = tid & 31;

    if (tid < 32) Bsm[tid] = g_bias[layer*G4 + gidx*32 + tid];

    // stage W once
    {
        const char* ws[2] = { (const char*)&g_W[0][((layer*CPL+gidx)*32)*256],
                              (const char*)&g_W[1][((layer*CPL+gidx)*32)*256] };
#pragma unroll
        for (int j = 0; j < 8; ++j){
            int id = j*NTHR + tid, arr = id>>10, rem = id&1023;
            int n = rem>>5, k0 = (rem&31)*8;
            cpa16((arr ? sWlo : sWhi) + (unsigned)(n*LDA + k0)*2u, ws[arr] + (n*256 + k0)*2);
        }
        cpa_fence();
    }
    __syncthreads();

    const int r16 = (wid >> 1) * 16;
    const int c16 = (wid & 1)  * 16;
    const int cb  = r16 + (lane >> 1);
    const int cs  = lane & 1;
    const int ug0 = gidx*8 + (wid & 1)*4 + cs*2;

    float bia[8];
#pragma unroll
    for (int j = 0; j < 8; ++j) bia[j] = Bsm[c16 + cs*8 + j];

    float cst0 = 0.f, cst1 = 0.f;

    unsigned* cnt_own   = &g_cnt[layer*Tn];
    unsigned* cnt_below = (layer > 0) ? &g_cnt[(layer-1)*Tn] : nullptr;

    for (int t = 0; t < Tn; ++t){
        // ---- per-warp poll of the two shared counters (R8 counters) ----
        if (lane == 0 && layer > 0){ while (ld_acq(&cnt_below[t]) < CPL) __nanosleep(16); }
        if (lane == 1 && t > 0)    { while (ld_acq(&cnt_own[t-1]) < CPL) __nanosleep(16); }
        __syncwarp();

        // ---- stage A into buf[t&1] (hi/lo) ----
        const unsigned aBuf = sA + (unsigned)(t & 1) * (2u*SM_ASZ);
        {
            const char* h0b[2]; const char* h1b[2];
            if (layer > 0){
                h0b[0] = (const char*)&g_hh[0][((size_t)(layer-1)*Tn + t)*Bn*Hn];
                h0b[1] = (const char*)&g_hh[1][((size_t)(layer-1)*Tn + t)*Bn*Hn];
            } else { h0b[0] = (const char*)g_emb[0]; h0b[1] = (const char*)g_emb[1]; }
            if (t > 0){
                h1b[0] = (const char*)&g_hh[0][((size_t)layer*Tn + (t-1))*Bn*Hn];
                h1b[1] = (const char*)&g_hh[1][((size_t)layer*Tn + (t-1))*Bn*Hn];
            }
            const int* xr = &g_xT[t*Bn];
#pragma unroll
            for (int j = 0; j < 16; ++j){
                int id = j*NTHR + tid, arr = id>>11, rem = id&2047;
                int b = rem>>5, k0 = (rem&31)*8;
                unsigned dst = aBuf + (unsigned)arr*SM_ASZ + (unsigned)(b*LDA + k0)*2u;
                if (k0 < 128){
                    const char* s = (layer==0) ? h0b[arr] + (xr[b]*Hn + k0)*2
                                               : h0b[arr] + (b*Hn + k0)*2;
                    cpa16(dst, s);
                } else if (t > 0){
                    cpa16(dst, h1b[arr] + (b*Hn + k0 - 128)*2);
                } else {
                    sts_zero16(dst);
                }
            }
            cpa_fence();
        }
        __syncthreads();   // all staging visible to all MMA warps

        // ---- tensor GEMM: 3 INDEPENDENT accumulator chains (HH, HL, LH) ----
        const __nv_bfloat16* Ahi = (const __nv_bfloat16*)(smraw + SM_A + (t&1)*(2*SM_ASZ));
        const __nv_bfloat16* Alo = (const __nv_bfloat16*)(smraw + SM_A + (t&1)*(2*SM_ASZ) + SM_ASZ);
        {
            wmma::fragment<wmma::accumulator, 16,16,16, float> aHH, aHL, aLH;
            wmma::fill_fragment(aHH, 0.0f);
            wmma::fill_fragment(aHL, 0.0f);
            wmma::fill_fragment(aLH, 0.0f);
#pragma unroll
            for (int ks = 0; ks < 16; ++ks){
                wmma::fragment<wmma::matrix_a, 16,16,16, __nv_bfloat16, wmma::row_major> ah, al;
                wmma::fragment<wmma::matrix_b, 16,16,16, __nv_bfloat16, wmma::col_major> bh, bl;
                wmma::load_matrix_sync(ah, Ahi + r16*LDA + ks*16, LDA);
                wmma::load_matrix_sync(al, Alo + r16*LDA + ks*16, LDA);
                wmma::load_matrix_sync(bh, Whi + c16*LDA + ks*16, LDA);
                wmma::load_matrix_sync(bl, Wlo + c16*LDA + ks*16, LDA);
                wmma::mma_sync(aHH, ah, bh, aHH);
                wmma::mma_sync(aHL, ah, bl, aHL);
                wmma::mma_sync(aLH, al, bh, aLH);
            }
#pragma unroll
            for (int i = 0; i < aHH.num_elements; ++i)
                aHH.x[i] += aHL.x[i] + aLH.x[i];
            wmma::store_matrix_sync(&Gsm[r16*LDG + c16], aHH, LDG, wmma::mem_row_major);
        }
        __syncwarp();      // warp-private Gsm tile visible within warp

        // ---- per-warp cell: 2 cells per lane ----
        {
            const float* gr = &Gsm[cb*LDG + c16 + cs*8];
            float4 gA = *(const float4*)(gr);
            float4 gB = *(const float4*)(gr + 4);
            float i0 = fsig (gA.x + bia[0]);
            float f0 = fsig (gA.y + bia[1]);
            float g0 = ftanh(gA.z + bia[2]);
            float o0 = fsig (gA.w + bia[3]);
            float i1 = fsig (gB.x + bia[4]);
            float f1 = fsig (gB.y + bia[5]);
            float g1 = ftanh(gB.z + bia[6]);
            float o1 = fsig (gB.w + bia[7]);
            cst0 = f0*cst0 + i0*g0;
            cst1 = f1*cst1 + i1*g1;
            float h0 = o0 * ftanh(cst0);
            float h1 = o1 * ftanh(cst1);

            __nv_bfloat16 bh0 = __float2bfloat16_rn(h0);
            __nv_bfloat16 bh1 = __float2bfloat16_rn(h1);
            __nv_bfloat16 bl0 = __float2bfloat16_rn(h0 - __bfloat162float(bh0));
            __nv_bfloat16 bl1 = __float2bfloat16_rn(h1 - __bfloat162float(bh1));
            unsigned hp = ((unsigned)__bfloat16_as_ushort(bh1)<<16) | __bfloat16_as_ushort(bh0);
            unsigned lp = ((unsigned)__bfloat16_as_ushort(bl1)<<16) | __bfloat16_as_ushort(bl0);

            size_t ho = (((size_t)layer*Tn + t)*Bn + cb)*Hn + ug0;
            *(unsigned*)&g_hh[0][ho] = hp;
            *(unsigned*)&g_hh[1][ho] = lp;
            if (layer == 7){
                g_h7[((size_t)t*Hn + ug0    )*Bn + cb] = h0;
                g_h7[((size_t)t*Hn + ug0 + 1)*Bn + cb] = h1;
            }
            if (t == Tn-1){
                *(float2*)&out[OUT_H_BASE + (layer*Bn + cb)*Hn + ug0] = make_float2(h0, h1);
                *(float2*)&out[OUT_C_BASE + (layer*Bn + cb)*Hn + ug0] = make_float2(cst0, cst1);
            }
        }

        // ---- R8-style release: barrier then one red.release ----
        __syncthreads();
        if (tid == 0) red_rel_add(&cnt_own[t]);
    }
}

// ---------------------------------------------------------------------------
__global__ void k_out(const float* __restrict__ w_out, const float* __restrict__ b_out,
                      float* __restrict__ out){
    extern __shared__ float sm[];
    float* Hs = sm;            // [128][64]
    float* Ws = sm + 8192;     // [128][65]
    int t = blockIdx.x, tid = threadIdx.x;
    const float4* s = (const float4*)&g_h7[(size_t)t*Hn*Bn];
    for (int i = tid; i < 2048; i += 256) ((float4*)Hs)[i] = s[i];
    for (int i = tid; i < Hn*On; i += 256) Ws[i] = w_out[i];
    __syncthreads();
    int b = tid & 63, og = tid >> 6;
    for (int o = og; o < On; o += 4){
        float acc = b_out[o];
#pragma unroll 8
        for (int k = 0; k < Hn; ++k) acc += Hs[k*Bn + b] * Ws[k*On + o];
        out[(b*Tn + t)*On + o] = acc;
    }
}

// ---------------------------------------------------------------------------
extern "C" void kernel_launch(void* const* d_in, const int* in_sizes, int n_in,
                              void* d_out, int out_size)
{
    const int*   x     = (const int*)  d_in[0];
    const float* embed = (const float*)d_in[1];
    const float* w_ih  = (const float*)d_in[2];
    const float* b_ih  = (const float*)d_in[3];
    const float* w_hh  = (const float*)d_in[4];
    const float* b_hh  = (const float*)d_in[5];
    const float* w_out = (const float*)d_in[6];
    const float* b_out = (const float*)d_in[7];
    float* out = (float*)d_out;

    size_t smem_lstm = SM_TOTAL;                                   // 178,304 B
    size_t smem_out  = (size_t)(8192 + Hn*On) * sizeof(float);
    cudaFuncSetAttribute(k_lstm, cudaFuncAttributeMaxDynamicSharedMemorySize, (int)smem_lstm);
    cudaFuncSetAttribute(k_out,  cudaFuncAttributeMaxDynamicSharedMemorySize, (int)smem_out);

    k_reset<<<128, 256>>>(x);
    k_prep_w<<<(Ln*G4*256)/256, 256>>>(w_ih, w_hh, b_ih, b_hh);
    k_prep_e<<<(Vn*Hn + 255)/256, 256>>>(embed);
    k_lstm<<<Ln*CPL, NTHR, smem_lstm>>>(out);
    k_out<<<Tn, 256, smem_out>>>(w_out, b_out, out);
}

// round 13
// speedup vs baseline: 1.6019x; 1.0680x over previous
#include <cuda_runtime.h>
#include <cuda_bf16.h>
#include <mma.h>
#include <math.h>

using namespace nvcuda;

#define Ln 8
#define Tn 512
#define Hn 128
#define Bn 64
#define G4 512
#define Vn 65
#define On 65
#define CPL 16
#define NTHR 256
#define LDA 264          // padded k-stride (elements)
#define LDG 36           // padded gate-row stride (floats)
#define OUT_MAIN (Bn*Tn*On)
#define OUT_H_BASE OUT_MAIN
#define OUT_C_BASE (OUT_MAIN + Ln*Bn*Hn)

// SMEM byte offsets (R8 layout, single A buffer)
#define SM_GSM   0
#define SM_BIAS  9216
#define SM_AHI   9472
#define SM_ALO   (SM_AHI + 64*LDA*2)
#define SM_WHI   (SM_ALO + 64*LDA*2)
#define SM_WLO   (SM_WHI + 32*LDA*2)
#define SM_TOTAL (SM_WLO + 32*LDA*2)     // 110848 B

__device__ __align__(16) __nv_bfloat16 g_hh[2][(size_t)Ln*Tn*Bn*Hn]; // [arr][l][t][b][u]
__device__ __align__(16) __nv_bfloat16 g_emb[2][Vn*Hn];
__device__ __align__(16) __nv_bfloat16 g_W[2][Ln*CPL*32*256];        // [arr][l][gidx][n][k]
__device__ float    g_bias[Ln*G4];
__device__ float    g_h7[(size_t)Tn*Hn*Bn];                          // [t][u][b]
__device__ int      g_xT[Tn*Bn];
__device__ unsigned g_cnt[Ln*Tn];

__device__ __forceinline__ unsigned ld_acq(const unsigned* p){
    unsigned v; asm volatile("ld.acquire.gpu.global.u32 %0, [%1];" : "=r"(v) : "l"(p) : "memory"); return v;
}
__device__ __forceinline__ void red_rel_add(unsigned* p){
    asm volatile("red.release.gpu.global.add.u32 [%0], 1;" :: "l"(p) : "memory");
}
__device__ __forceinline__ float fsig(float x){ return __fdividef(1.f, 1.f + __expf(-x)); }
__device__ __forceinline__ float ftanh(float x){ return 1.f - __fdividef(2.f, __expf(2.f*x)+1.f); }
__device__ __forceinline__ unsigned smaddr(const void* p){
    unsigned a; asm("{ .reg .u64 t; cvta.to.shared.u64 t, %1; cvt.u32.u64 %0, t; }" : "=r"(a) : "l"(p)); return a;
}
__device__ __forceinline__ void cpa16(unsigned dst, const void* src){
    asm volatile("cp.async.cg.shared.global [%0], [%1], 16;" :: "r"(dst), "l"(src) : "memory");
}
__device__ __forceinline__ void cpa_fence(){
    asm volatile("cp.async.commit_group;" ::: "memory");
    asm volatile("cp.async.wait_group 0;" ::: "memory");
}
__device__ __forceinline__ void sts_zero16(unsigned dst){
    asm volatile("st.shared.v4.b32 [%0], {%1,%1,%1,%1};" :: "r"(dst), "r"(0u) : "memory");
}

// ---------------------------------------------------------------------------
__global__ void k_reset(const int* __restrict__ x){
    int i = blockIdx.x*blockDim.x + threadIdx.x;
    if (i < Ln*Tn) g_cnt[i] = 0u;
    if (i < Tn*Bn){ int t = i/Bn, b = i%Bn; g_xT[i] = x[b*Tn + t]; }
}

// W reorder + hi/lo split: g_W[arr][l][gidx][n][k], n = ul*4 + gate
__global__ void k_prep_w(const float* __restrict__ w_ih, const float* __restrict__ w_hh,
                         const float* __restrict__ b_ih, const float* __restrict__ b_hh){
    int gid = blockIdx.x*256 + threadIdx.x;
    if (gid >= Ln*G4*256) return;
    int k = gid & 255, col = (gid>>8)&511, l = gid>>17;
    int gate = col>>7, u = col&127, gidx = u>>3, ul = u&7, n = ul*4+gate;
    float w = (k < Hn) ? w_ih[(l*Hn+k)*G4+col] : w_hh[(l*Hn+k-Hn)*G4+col];
    __nv_bfloat16 hi = __float2bfloat16_rn(w);
    int idx = ((l*CPL+gidx)*32 + n)*256 + k;
    g_W[0][idx] = hi;
    g_W[1][idx] = __float2bfloat16_rn(w - __bfloat162float(hi));
    if (k == 0) g_bias[l*G4 + gidx*32 + n] = b_ih[l*G4+col] + b_hh[l*G4+col];
}

__global__ void k_prep_e(const float* __restrict__ embed){
    int i = blockIdx.x*256 + threadIdx.x;
    if (i < Vn*Hn){
        float e = embed[i];
        __nv_bfloat16 hi = __float2bfloat16_rn(e);
        g_emb[0][i] = hi;
        g_emb[1][i] = __float2bfloat16_rn(e - __bfloat162float(hi));
    }
}

// ---------------------------------------------------------------------------
// Persistent wavefront LSTM (R8 skeleton); wmma bf16 3-term, 3 indep chains;
// cell spread over all 8 warps with vectorized Gsm reads.
__global__ void __launch_bounds__(NTHR, 1) k_lstm(float* __restrict__ out)
{
    extern __shared__ char smraw[];
    float* Gsm = (float*)(smraw + SM_GSM);                 // [64][LDG]
    float* Bsm = (float*)(smraw + SM_BIAS);                // [32]
    __nv_bfloat16* Ahi = (__nv_bfloat16*)(smraw + SM_AHI); // [64][LDA]
    __nv_bfloat16* Alo = (__nv_bfloat16*)(smraw + SM_ALO);
    __nv_bfloat16* Whi = (__nv_bfloat16*)(smraw + SM_WHI); // [32][LDA]
    __nv_bfloat16* Wlo = (__nv_bfloat16*)(smraw + SM_WLO);
    const unsigned sAhi = smaddr(Ahi), sAlo = smaddr(Alo);
    const unsigned sWhi = smaddr(Whi), sWlo = smaddr(Wlo);

    const int layer = blockIdx.x >> 4;
    const int gidx  = blockIdx.x & 15;
    const int tid   = threadIdx.x;
    const int wid   = tid >> 5;

    if (tid < 32) Bsm[tid] = g_bias[layer*G4 + gidx*32 + tid];

    // ---- stage W (once)
    {
        const char* ws[2] = { (const char*)&g_W[0][((layer*CPL+gidx)*32)*256],
                              (const char*)&g_W[1][((layer*CPL+gidx)*32)*256] };
#pragma unroll
        for (int j = 0; j < 8; ++j){
            int id = j*NTHR + tid, arr = id>>10, rem = id&1023;
            int n = rem>>5, k0 = (rem&31)*8;
            cpa16((arr ? sWlo : sWhi) + (unsigned)(n*LDA + k0)*2u, ws[arr] + (n*256 + k0)*2);
        }
        cpa_fence();
    }
    __syncthreads();

    // wmma tile assignment
    const int r16 = (wid >> 1) * 16;
    const int c16 = (wid & 1)  * 16;

    // cell mapping: thread -> (b, unit pair)
    const int cbb = tid & 63;               // batch
    const int cup = tid >> 6;               // unit pair 0..3
    const int ug  = gidx*8 + cup*2;         // global unit (even)

    float cst0 = 0.f, cst1 = 0.f;

    unsigned* cnt_own   = &g_cnt[layer*Tn];
    unsigned* cnt_below = (layer > 0) ? &g_cnt[(layer-1)*Tn] : nullptr;

    for (int t = 0; t < Tn; ++t){
        // ---- wait deps (R8 scheme) ----
        if (tid == 0 && layer > 0){ while (ld_acq(&cnt_below[t]) < CPL) __nanosleep(16); }
        if (tid == 32 && t > 0)   { while (ld_acq(&cnt_own[t-1]) < CPL) __nanosleep(16); }
        __syncthreads();

        // ---- stage A [64][256] hi/lo ----
        {
            const char* h0b[2]; const char* h1b[2];
            if (layer > 0){
                h0b[0] = (const char*)&g_hh[0][((size_t)(layer-1)*Tn + t)*Bn*Hn];
                h0b[1] = (const char*)&g_hh[1][((size_t)(layer-1)*Tn + t)*Bn*Hn];
            } else { h0b[0] = (const char*)g_emb[0]; h0b[1] = (const char*)g_emb[1]; }
            if (t > 0){
                h1b[0] = (const char*)&g_hh[0][((size_t)layer*Tn + (t-1))*Bn*Hn];
                h1b[1] = (const char*)&g_hh[1][((size_t)layer*Tn + (t-1))*Bn*Hn];
            }
            const int* xr = &g_xT[t*Bn];
#pragma unroll
            for (int j = 0; j < 16; ++j){
                int id = j*NTHR + tid, arr = id>>11, rem = id&2047;
                int b = rem>>5, k0 = (rem&31)*8;
                unsigned dst = (arr ? sAlo : sAhi) + (unsigned)(b*LDA + k0)*2u;
                if (k0 < 128){
                    const char* s = (layer==0) ? h0b[arr] + (xr[b]*Hn + k0)*2
                                               : h0b[arr] + (b*Hn + k0)*2;
                    cpa16(dst, s);
                } else if (t > 0){
                    cpa16(dst, h1b[arr] + (b*Hn + k0 - 128)*2);
                } else {
                    sts_zero16(dst);
                }
            }
            cpa_fence();
        }
        __syncthreads();

        // ---- tensor GEMM: 3 INDEPENDENT accumulator chains ----
        {
            wmma::fragment<wmma::accumulator, 16,16,16, float> aHH, aHL, aLH;
            wmma::fill_fragment(aHH, 0.0f);
            wmma::fill_fragment(aHL, 0.0f);
            wmma::fill_fragment(aLH, 0.0f);
#pragma unroll
            for (int ks = 0; ks < 16; ++ks){
                wmma::fragment<wmma::matrix_a, 16,16,16, __nv_bfloat16, wmma::row_major> ah, al;
                wmma::fragment<wmma::matrix_b, 16,16,16, __nv_bfloat16, wmma::col_major> bh, bl;
                wmma::load_matrix_sync(ah, Ahi + r16*LDA + ks*16, LDA);
                wmma::load_matrix_sync(al, Alo + r16*LDA + ks*16, LDA);
                wmma::load_matrix_sync(bh, Whi + c16*LDA + ks*16, LDA);
                wmma::load_matrix_sync(bl, Wlo + c16*LDA + ks*16, LDA);
                wmma::mma_sync(aHH, ah, bh, aHH);
                wmma::mma_sync(aHL, ah, bl, aHL);
                wmma::mma_sync(aLH, al, bh, aLH);
            }
#pragma unroll
            for (int i = 0; i < aHH.num_elements; ++i)
                aHH.x[i] += aHL.x[i] + aLH.x[i];
            wmma::store_matrix_sync(&Gsm[r16*LDG + c16], aHH, LDG, wmma::mem_row_major);
        }
        __syncthreads();

        // ---- cell: all 8 warps, 2 cells per thread, vectorized Gsm reads ----
        {
            const float* gr = &Gsm[cbb*LDG + cup*8];
            float4 gA = *(const float4*)(gr);        // unit ug:   i f g o
            float4 gB = *(const float4*)(gr + 4);    // unit ug+1: i f g o
            const float* bp = &Bsm[cup*8];
            float i0 = fsig (gA.x + bp[0]);
            float f0 = fsig (gA.y + bp[1]);
            float g0 = ftanh(gA.z + bp[2]);
            float o0 = fsig (gA.w + bp[3]);
            float i1 = fsig (gB.x + bp[4]);
            float f1 = fsig (gB.y + bp[5]);
            float g1 = ftanh(gB.z + bp[6]);
            float o1 = fsig (gB.w + bp[7]);
            cst0 = f0*cst0 + i0*g0;
            cst1 = f1*cst1 + i1*g1;
            float h0 = o0 * ftanh(cst0);
            float h1 = o1 * ftanh(cst1);

            __nv_bfloat16 bh0 = __float2bfloat16_rn(h0);
            __nv_bfloat16 bh1 = __float2bfloat16_rn(h1);
            __nv_bfloat16 bl0 = __float2bfloat16_rn(h0 - __bfloat162float(bh0));
            __nv_bfloat16 bl1 = __float2bfloat16_rn(h1 - __bfloat162float(bh1));
            unsigned hp = ((unsigned)__bfloat16_as_ushort(bh1)<<16) | __bfloat16_as_ushort(bh0);
            unsigned lp = ((unsigned)__bfloat16_as_ushort(bl1)<<16) | __bfloat16_as_ushort(bl0);

            size_t ho = (((size_t)layer*Tn + t)*Bn + cbb)*Hn + ug;
            *(unsigned*)&g_hh[0][ho] = hp;
            *(unsigned*)&g_hh[1][ho] = lp;
            if (layer == 7){
                g_h7[((size_t)t*Hn + ug    )*Bn + cbb] = h0;
                g_h7[((size_t)t*Hn + ug + 1)*Bn + cbb] = h1;
            }
            if (t == Tn-1){
                *(float2*)&out[OUT_H_BASE + (layer*Bn + cbb)*Hn + ug] = make_float2(h0, h1);
                *(float2*)&out[OUT_C_BASE + (layer*Bn + cbb)*Hn + ug] = make_float2(cst0, cst1);
            }
        }
        __syncthreads();   // all h-stores done before release
        if (tid == 0) red_rel_add(&cnt_own[t]);
    }
}

// ---------------------------------------------------------------------------
__global__ void k_out(const float* __restrict__ w_out, const float* __restrict__ b_out,
                      float* __restrict__ out){
    extern __shared__ float sm[];
    float* Hs = sm;            // [128][64]
    float* Ws = sm + 8192;     // [128][65]
    int t = blockIdx.x, tid = threadIdx.x;
    const float4* s = (const float4*)&g_h7[(size_t)t*Hn*Bn];
    for (int i = tid; i < 2048; i += 256) ((float4*)Hs)[i] = s[i];
    for (int i = tid; i < Hn*On; i += 256) Ws[i] = w_out[i];
    __syncthreads();
    int b = tid & 63, og = tid >> 6;
    for (int o = og; o < On; o += 4){
        float acc = b_out[o];
#pragma unroll 8
        for (int k = 0; k < Hn; ++k) acc += Hs[k*Bn + b] * Ws[k*On + o];
        out[(b*Tn + t)*On + o] = acc;
    }
}

// ---------------------------------------------------------------------------
extern "C" void kernel_launch(void* const* d_in, const int* in_sizes, int n_in,
                              void* d_out, int out_size)
{
    const int*   x     = (const int*)  d_in[0];
    const float* embed = (const float*)d_in[1];
    const float* w_ih  = (const float*)d_in[2];
    const float* b_ih  = (const float*)d_in[3];
    const float* w_hh  = (const float*)d_in[4];
    const float* b_hh  = (const float*)d_in[5];
    const float* w_out = (const float*)d_in[6];
    const float* b_out = (const float*)d_in[7];
    float* out = (float*)d_out;

    size_t smem_lstm = SM_TOTAL;                                   // 110,848 B
    size_t smem_out  = (size_t)(8192 + Hn*On) * sizeof(float);
    cudaFuncSetAttribute(k_lstm, cudaFuncAttributeMaxDynamicSharedMemorySize, (int)smem_lstm);
    cudaFuncSetAttribute(k_out,  cudaFuncAttributeMaxDynamicSharedMemorySize, (int)smem_out);

    k_reset<<<128, 256>>>(x);
    k_prep_w<<<(Ln*G4*256)/256, 256>>>(w_ih, w_hh, b_ih, b_hh);
    k_prep_e<<<(Vn*Hn + 255)/256, 256>>>(embed);
    k_lstm<<<Ln*CPL, NTHR, smem_lstm>>>(out);
    k_out<<<Tn, 256, smem_out>>>(w_out, b_out, out);
}

// round 14
// speedup vs baseline: 1.6877x; 1.0536x over previous
#include <cuda_runtime.h>
#include <cuda_bf16.h>
#include <mma.h>
#include <math.h>

using namespace nvcuda;

#define Ln 8
#define Tn 512
#define Hn 128
#define Bn 64
#define G4 512
#define Vn 65
#define On 65
#define CPL 16
#define NTHR 256
#define LDA 264          // padded k-stride (elements)
#define LDG 36           // padded gate-row stride (floats)
#define OUT_MAIN (Bn*Tn*On)
#define OUT_H_BASE OUT_MAIN
#define OUT_C_BASE (OUT_MAIN + Ln*Bn*Hn)

// SMEM byte offsets (R8 layout, single A buffer)
#define SM_GSM   0
#define SM_BIAS  9216
#define SM_AHI   9472
#define SM_ALO   (SM_AHI + 64*LDA*2)
#define SM_WHI   (SM_ALO + 64*LDA*2)
#define SM_WLO   (SM_WHI + 32*LDA*2)
#define SM_TOTAL (SM_WLO + 32*LDA*2)     // 110848 B

__device__ __align__(16) __nv_bfloat16 g_hh[2][(size_t)Ln*Tn*Bn*Hn]; // [arr][l][t][b][u]
__device__ __align__(16) __nv_bfloat16 g_emb[2][Vn*Hn];
__device__ __align__(16) __nv_bfloat16 g_W[2][Ln*CPL*32*256];        // [arr][l][gidx][n][k]
__device__ float    g_bias[Ln*G4];
__device__ float    g_h7[(size_t)Tn*Hn*Bn];                          // [t][u][b]
__device__ int      g_xT[Tn*Bn];
__device__ unsigned g_cnt[Ln*Tn];

__device__ __forceinline__ unsigned ld_acq(const unsigned* p){
    unsigned v; asm volatile("ld.acquire.gpu.global.u32 %0, [%1];" : "=r"(v) : "l"(p) : "memory"); return v;
}
__device__ __forceinline__ void red_rel_add(unsigned* p){
    asm volatile("red.release.gpu.global.add.u32 [%0], 1;" :: "l"(p) : "memory");
}
__device__ __forceinline__ float fsig(float x){ return __fdividef(1.f, 1.f + __expf(-x)); }
__device__ __forceinline__ float ftanh(float x){ return 1.f - __fdividef(2.f, __expf(2.f*x)+1.f); }
__device__ __forceinline__ unsigned smaddr(const void* p){
    unsigned a; asm("{ .reg .u64 t; cvta.to.shared.u64 t, %1; cvt.u32.u64 %0, t; }" : "=r"(a) : "l"(p)); return a;
}
__device__ __forceinline__ void cpa16(unsigned dst, const void* src){
    asm volatile("cp.async.cg.shared.global [%0], [%1], 16;" :: "r"(dst), "l"(src) : "memory");
}
__device__ __forceinline__ void cpa_fence(){
    asm volatile("cp.async.commit_group;" ::: "memory");
    asm volatile("cp.async.wait_group 0;" ::: "memory");
}
__device__ __forceinline__ void sts_zero16(unsigned dst){
    asm volatile("st.shared.v4.b32 [%0], {%1,%1,%1,%1};" :: "r"(dst), "r"(0u) : "memory");
}

// ---------------------------------------------------------------------------
__global__ void k_reset(const int* __restrict__ x){
    int i = blockIdx.x*blockDim.x + threadIdx.x;
    if (i < Ln*Tn) g_cnt[i] = 0u;
    if (i < Tn*Bn){ int t = i/Bn, b = i%Bn; g_xT[i] = x[b*Tn + t]; }
}

// W reorder + hi/lo split: g_W[arr][l][gidx][n][k], n = ul*4 + gate
__global__ void k_prep_w(const float* __restrict__ w_ih, const float* __restrict__ w_hh,
                         const float* __restrict__ b_ih, const float* __restrict__ b_hh){
    int gid = blockIdx.x*256 + threadIdx.x;
    if (gid >= Ln*G4*256) return;
    int k = gid & 255, col = (gid>>8)&511, l = gid>>17;
    int gate = col>>7, u = col&127, gidx = u>>3, ul = u&7, n = ul*4+gate;
    float w = (k < Hn) ? w_ih[(l*Hn+k)*G4+col] : w_hh[(l*Hn+k-Hn)*G4+col];
    __nv_bfloat16 hi = __float2bfloat16_rn(w);
    int idx = ((l*CPL+gidx)*32 + n)*256 + k;
    g_W[0][idx] = hi;
    g_W[1][idx] = __float2bfloat16_rn(w - __bfloat162float(hi));
    if (k == 0) g_bias[l*G4 + gidx*32 + n] = b_ih[l*G4+col] + b_hh[l*G4+col];
}

__global__ void k_prep_e(const float* __restrict__ embed){
    int i = blockIdx.x*256 + threadIdx.x;
    if (i < Vn*Hn){
        float e = embed[i];
        __nv_bfloat16 hi = __float2bfloat16_rn(e);
        g_emb[0][i] = hi;
        g_emb[1][i] = __float2bfloat16_rn(e - __bfloat162float(hi));
    }
}

// ---------------------------------------------------------------------------
// Persistent wavefront LSTM; wmma bf16 3-term; 2-barrier beat:
// per-warp poll, staged A (bar), MMA, per-warp cell, bar + release.
__global__ void __launch_bounds__(NTHR, 1) k_lstm(float* __restrict__ out)
{
    extern __shared__ char smraw[];
    float* Gsm = (float*)(smraw + SM_GSM);                 // [64][LDG]
    float* Bsm = (float*)(smraw + SM_BIAS);                // [32]
    __nv_bfloat16* Ahi = (__nv_bfloat16*)(smraw + SM_AHI); // [64][LDA]
    __nv_bfloat16* Alo = (__nv_bfloat16*)(smraw + SM_ALO);
    __nv_bfloat16* Whi = (__nv_bfloat16*)(smraw + SM_WHI); // [32][LDA]
    __nv_bfloat16* Wlo = (__nv_bfloat16*)(smraw + SM_WLO);
    const unsigned sAhi = smaddr(Ahi), sAlo = smaddr(Alo);
    const unsigned sWhi = smaddr(Whi), sWlo = smaddr(Wlo);

    const int layer = blockIdx.x >> 4;
    const int gidx  = blockIdx.x & 15;
    const int tid   = threadIdx.x;
    const int wid   = tid >> 5;
    const int lane  = tid & 31;

    if (tid < 32) Bsm[tid] = g_bias[layer*G4 + gidx*32 + tid];

    // ---- stage W (once)
    {
        const char* ws[2] = { (const char*)&g_W[0][((layer*CPL+gidx)*32)*256],
                              (const char*)&g_W[1][((layer*CPL+gidx)*32)*256] };
#pragma unroll
        for (int j = 0; j < 8; ++j){
            int id = j*NTHR + tid, arr = id>>10, rem = id&1023;
            int n = rem>>5, k0 = (rem&31)*8;
            cpa16((arr ? sWlo : sWhi) + (unsigned)(n*LDA + k0)*2u, ws[arr] + (n*256 + k0)*2);
        }
        cpa_fence();
    }
    __syncthreads();

    // wmma tile: rows [r16, r16+16), cols [c16, c16+16)
    const int r16 = (wid >> 1) * 16;
    const int c16 = (wid & 1)  * 16;
    // per-warp cell mapping (R9): lane -> batch cb, 2 units starting at ug0
    const int cb  = r16 + (lane >> 1);
    const int cs  = lane & 1;
    const int ug0 = gidx*8 + (wid & 1)*4 + cs*2;

    float bia[8];
#pragma unroll
    for (int j = 0; j < 8; ++j) bia[j] = Bsm[c16 + cs*8 + j];

    float cst0 = 0.f, cst1 = 0.f;

    unsigned* cnt_own   = &g_cnt[layer*Tn];
    unsigned* cnt_below = (layer > 0) ? &g_cnt[(layer-1)*Tn] : nullptr;

    for (int t = 0; t < Tn; ++t){
        // ---- per-warp poll (lanes 0/1), no CTA barrier ----
        if (lane == 0 && layer > 0){ while (ld_acq(&cnt_below[t]) < CPL) __nanosleep(8); }
        if (lane == 1 && t > 0)    { while (ld_acq(&cnt_own[t-1]) < CPL) __nanosleep(8); }
        __syncwarp();

        // ---- stage A [64][256] hi/lo (each thread 16 chunks) ----
        {
            const char* h0b[2]; const char* h1b[2];
            if (layer > 0){
                h0b[0] = (const char*)&g_hh[0][((size_t)(layer-1)*Tn + t)*Bn*Hn];
                h0b[1] = (const char*)&g_hh[1][((size_t)(layer-1)*Tn + t)*Bn*Hn];
            } else { h0b[0] = (const char*)g_emb[0]; h0b[1] = (const char*)g_emb[1]; }
            if (t > 0){
                h1b[0] = (const char*)&g_hh[0][((size_t)layer*Tn + (t-1))*Bn*Hn];
                h1b[1] = (const char*)&g_hh[1][((size_t)layer*Tn + (t-1))*Bn*Hn];
            }
            const int* xr = &g_xT[t*Bn];
#pragma unroll
            for (int j = 0; j < 16; ++j){
                int id = j*NTHR + tid, arr = id>>11, rem = id&2047;
                int b = rem>>5, k0 = (rem&31)*8;
                unsigned dst = (arr ? sAlo : sAhi) + (unsigned)(b*LDA + k0)*2u;
                if (k0 < 128){
                    const char* s = (layer==0) ? h0b[arr] + (xr[b]*Hn + k0)*2
                                               : h0b[arr] + (b*Hn + k0)*2;
                    cpa16(dst, s);
                } else if (t > 0){
                    cpa16(dst, h1b[arr] + (b*Hn + k0 - 128)*2);
                } else {
                    sts_zero16(dst);
                }
            }
            cpa_fence();
        }
        __syncthreads();   // barrier 1: all A staging visible to all MMA warps

        // ---- tensor GEMM (single acc chain, 3 terms) ----
        {
            wmma::fragment<wmma::accumulator, 16,16,16, float> acc;
            wmma::fill_fragment(acc, 0.0f);
#pragma unroll
            for (int ks = 0; ks < 16; ++ks){
                wmma::fragment<wmma::matrix_a, 16,16,16, __nv_bfloat16, wmma::row_major> ah, al;
                wmma::fragment<wmma::matrix_b, 16,16,16, __nv_bfloat16, wmma::col_major> bh, bl;
                wmma::load_matrix_sync(ah, Ahi + r16*LDA + ks*16, LDA);
                wmma::load_matrix_sync(al, Alo + r16*LDA + ks*16, LDA);
                wmma::load_matrix_sync(bh, Whi + c16*LDA + ks*16, LDA);
                wmma::load_matrix_sync(bl, Wlo + c16*LDA + ks*16, LDA);
                wmma::mma_sync(acc, ah, bh, acc);
                wmma::mma_sync(acc, ah, bl, acc);
                wmma::mma_sync(acc, al, bh, acc);
            }
            wmma::store_matrix_sync(&Gsm[r16*LDG + c16], acc, LDG, wmma::mem_row_major);
        }
        __syncwarp();      // warp-private Gsm tile visible within warp

        // ---- per-warp cell: 2 cells per lane ----
        {
            const float* gr = &Gsm[cb*LDG + c16 + cs*8];
            float4 gA = *(const float4*)(gr);        // unit ug0:   i f g o
            float4 gB = *(const float4*)(gr + 4);    // unit ug0+1: i f g o
            float i0 = fsig (gA.x + bia[0]);
            float f0 = fsig (gA.y + bia[1]);
            float g0 = ftanh(gA.z + bia[2]);
            float o0 = fsig (gA.w + bia[3]);
            float i1 = fsig (gB.x + bia[4]);
            float f1 = fsig (gB.y + bia[5]);
            float g1 = ftanh(gB.z + bia[6]);
            float o1 = fsig (gB.w + bia[7]);
            cst0 = f0*cst0 + i0*g0;
            cst1 = f1*cst1 + i1*g1;
            float h0 = o0 * ftanh(cst0);
            float h1 = o1 * ftanh(cst1);

            __nv_bfloat16 bh0 = __float2bfloat16_rn(h0);
            __nv_bfloat16 bh1 = __float2bfloat16_rn(h1);
            __nv_bfloat16 bl0 = __float2bfloat16_rn(h0 - __bfloat162float(bh0));
            __nv_bfloat16 bl1 = __float2bfloat16_rn(h1 - __bfloat162float(bh1));
            unsigned hp = ((unsigned)__bfloat16_as_ushort(bh1)<<16) | __bfloat16_as_ushort(bh0);
            unsigned lp = ((unsigned)__bfloat16_as_ushort(bl1)<<16) | __bfloat16_as_ushort(bl0);

            size_t ho = (((size_t)layer*Tn + t)*Bn + cb)*Hn + ug0;
            *(unsigned*)&g_hh[0][ho] = hp;
            *(unsigned*)&g_hh[1][ho] = lp;
            if (layer == 7){
                g_h7[((size_t)t*Hn + ug0    )*Bn + cb] = h0;
                g_h7[((size_t)t*Hn + ug0 + 1)*Bn + cb] = h1;
            }
            if (t == Tn-1){
                *(float2*)&out[OUT_H_BASE + (layer*Bn + cb)*Hn + ug0] = make_float2(h0, h1);
                *(float2*)&out[OUT_C_BASE + (layer*Bn + cb)*Hn + ug0] = make_float2(cst0, cst1);
            }
        }

        // ---- barrier 2: MMA reads + h-stores done; then single release ----
        __syncthreads();
        if (tid == 0) red_rel_add(&cnt_own[t]);
    }
}

// ---------------------------------------------------------------------------
__global__ void k_out(const float* __restrict__ w_out, const float* __restrict__ b_out,
                      float* __restrict__ out){
    extern __shared__ float sm[];
    float* Hs = sm;            // [128][64]
    float* Ws = sm + 8192;     // [128][65]
    int t = blockIdx.x, tid = threadIdx.x;
    const float4* s = (const float4*)&g_h7[(size_t)t*Hn*Bn];
    for (int i = tid; i < 2048; i += 256) ((float4*)Hs)[i] = s[i];
    for (int i = tid; i < Hn*On; i += 256) Ws[i] = w_out[i];
    __syncthreads();
    int b = tid & 63, og = tid >> 6;
    for (int o = og; o < On; o += 4){
        float acc = b_out[o];
#pragma unroll 8
        for (int k = 0; k < Hn; ++k) acc += Hs[k*Bn + b] * Ws[k*On + o];
        out[(b*Tn + t)*On + o] = acc;
    }
}

// ---------------------------------------------------------------------------
extern "C" void kernel_launch(void* const* d_in, const int* in_sizes, int n_in,
                              void* d_out, int out_size)
{
    const int*   x     = (const int*)  d_in[0];
    const float* embed = (const float*)d_in[1];
    const float* w_ih  = (const float*)d_in[2];
    const float* b_ih  = (const float*)d_in[3];
    const float* w_hh  = (const float*)d_in[4];
    const float* b_hh  = (const float*)d_in[5];
    const float* w_out = (const float*)d_in[6];
    const float* b_out = (const float*)d_in[7];
    float* out = (float*)d_out;

    size_t smem_lstm = SM_TOTAL;                                   // 110,848 B
    size_t smem_out  = (size_t)(8192 + Hn*On) * sizeof(float);
    cudaFuncSetAttribute(k_lstm, cudaFuncAttributeMaxDynamicSharedMemorySize, (int)smem_lstm);
    cudaFuncSetAttribute(k_out,  cudaFuncAttributeMaxDynamicSharedMemorySize, (int)smem_out);

    k_reset<<<128, 256>>>(x);
    k_prep_w<<<(Ln*G4*256)/256, 256>>>(w_ih, w_hh, b_ih, b_hh);
    k_prep_e<<<(Vn*Hn + 255)/256, 256>>>(embed);
    k_lstm<<<Ln*CPL, NTHR, smem_lstm>>>(out);
    k_out<<<Tn, 256, smem_out>>>(w_out, b_out, out);
}

// round 16
// speedup vs baseline: 2.5312x; 1.4998x over previous
#include <cuda_runtime.h>
#include <cuda_bf16.h>
#include <mma.h>
#include <math.h>

using namespace nvcuda;

#define Ln 8
#define Tn 512
#define Hn 128
#define Bn 64
#define G4 512
#define Vn 65
#define On 65
#define CPL 16
#define NTHR 256
#define LDA 264          // padded k-stride (elements)
#define LDG 36           // padded gate-row stride (floats)
#define OUT_MAIN (Bn*Tn*On)
#define OUT_H_BASE OUT_MAIN
#define OUT_C_BASE (OUT_MAIN + Ln*Bn*Hn)

// SMEM byte offsets (layer CTAs)
#define SM_GSM   0
#define SM_BIAS  9216
#define SM_AHI   9472
#define SM_ALO   (SM_AHI + 64*LDA*2)
#define SM_WHI   (SM_ALO + 64*LDA*2)
#define SM_WLO   (SM_WHI + 32*LDA*2)
#define SM_TOTAL (SM_WLO + 32*LDA*2)     // 110848 B

// out-CTA smem layout (within same dynamic smem)
#define SMO_W    0                       // [128][65] fp32 = 33280 B
#define SMO_B    33280                   // [65] fp32
#define SMO_H    33600                   // [4][128] fp32 = 2048 B

__device__ __align__(16) __nv_bfloat16 g_hh[2][(size_t)Ln*Tn*Bn*Hn]; // [arr][l][t][b][u]
__device__ __align__(16) __nv_bfloat16 g_emb[2][Vn*Hn];
__device__ __align__(16) __nv_bfloat16 g_W[2][Ln*CPL*32*256];        // [arr][l][gidx][n][k]
__device__ float    g_bias[Ln*G4];
__device__ int      g_xT[Tn*Bn];
__device__ unsigned g_cnt[Ln*Tn];

__device__ __forceinline__ unsigned ld_acq(const unsigned* p){
    unsigned v; asm volatile("ld.acquire.gpu.global.u32 %0, [%1];" : "=r"(v) : "l"(p) : "memory"); return v;
}
__device__ __forceinline__ void red_rel_add(unsigned* p){
    asm volatile("red.release.gpu.global.add.u32 [%0], 1;" :: "l"(p) : "memory");
}
__device__ __forceinline__ float fsig(float x){ return __fdividef(1.f, 1.f + __expf(-x)); }
__device__ __forceinline__ float ftanh(float x){ return 1.f - __fdividef(2.f, __expf(2.f*x)+1.f); }
__device__ __forceinline__ unsigned smaddr(const void* p){
    unsigned a; asm("{ .reg .u64 t; cvta.to.shared.u64 t, %1; cvt.u32.u64 %0, t; }" : "=r"(a) : "l"(p)); return a;
}
__device__ __forceinline__ void cpa16(unsigned dst, const void* src){
    asm volatile("cp.async.cg.shared.global [%0], [%1], 16;" :: "r"(dst), "l"(src) : "memory");
}
__device__ __forceinline__ void cpa_commit(){
    asm volatile("cp.async.commit_group;" ::: "memory");
}
__device__ __forceinline__ void cpa_wait1(){
    asm volatile("cp.async.wait_group 1;" ::: "memory");
}
__device__ __forceinline__ void cpa_wait0(){
    asm volatile("cp.async.wait_group 0;" ::: "memory");
}
__device__ __forceinline__ void sts_zero16(unsigned dst){
    asm volatile("st.shared.v4.b32 [%0], {%1,%1,%1,%1};" :: "r"(dst), "r"(0u) : "memory");
}

// ---------------------------------------------------------------------------
__global__ void k_reset(const int* __restrict__ x){
    int i = blockIdx.x*blockDim.x + threadIdx.x;
    if (i < Ln*Tn) g_cnt[i] = 0u;
    if (i < Tn*Bn){ int t = i/Bn, b = i%Bn; g_xT[i] = x[b*Tn + t]; }
}

// W reorder + hi/lo split: g_W[arr][l][gidx][n][k], n = ul*4 + gate
__global__ void k_prep_w(const float* __restrict__ w_ih, const float* __restrict__ w_hh,
                         const float* __restrict__ b_ih, const float* __restrict__ b_hh){
    int gid = blockIdx.x*256 + threadIdx.x;
    if (gid >= Ln*G4*256) return;
    int k = gid & 255, col = (gid>>8)&511, l = gid>>17;
    int gate = col>>7, u = col&127, gidx = u>>3, ul = u&7, n = ul*4+gate;
    float w = (k < Hn) ? w_ih[(l*Hn+k)*G4+col] : w_hh[(l*Hn+k-Hn)*G4+col];
    __nv_bfloat16 hi = __float2bfloat16_rn(w);
    int idx = ((l*CPL+gidx)*32 + n)*256 + k;
    g_W[0][idx] = hi;
    g_W[1][idx] = __float2bfloat16_rn(w - __bfloat162float(hi));
    if (k == 0) g_bias[l*G4 + gidx*32 + n] = b_ih[l*G4+col] + b_hh[l*G4+col];
}

__global__ void k_prep_e(const float* __restrict__ embed){
    int i = blockIdx.x*256 + threadIdx.x;
    if (i < Vn*Hn){
        float e = embed[i];
        __nv_bfloat16 hi = __float2bfloat16_rn(e);
        g_emb[0][i] = hi;
        g_emb[1][i] = __float2bfloat16_rn(e - __bfloat162float(hi));
    }
}

// ---------------------------------------------------------------------------
// Persistent wavefront LSTM + fused output projection.
// Blocks 0..127: layer CTAs (wmma bf16 3-term, split-group staging overlap).
// Blocks 128..143: out-CTAs (poll layer-7 counter, project 4 batches x 65 out).
__global__ void __launch_bounds__(NTHR, 1) k_lstm(float* __restrict__ out,
                                                  const float* __restrict__ w_out,
                                                  const float* __restrict__ b_out)
{
    extern __shared__ char smraw[];
    const int tid  = threadIdx.x;

    // ======================= OUT-PROJECTION CTAs ==========================
    if (blockIdx.x >= 128){
        const int og4 = blockIdx.x - 128;        // batch group: batches [4*og4, 4*og4+4)
        float* Wo = (float*)(smraw + SMO_W);     // [128][65]
        float* Bo = (float*)(smraw + SMO_B);     // [65]
        float* Hsm = (float*)(smraw + SMO_H);    // [4][128]

        for (int i = tid; i < Hn*On; i += NTHR) Wo[i] = w_out[i];
        if (tid < On) Bo[tid] = b_out[tid];
        __syncthreads();

        const unsigned* cnt7 = &g_cnt[7*Tn];

        for (int t = 0; t < Tn; ++t){
            if (tid == 0){ while (ld_acq(&cnt7[t]) < CPL) __nanosleep(32); }
            __syncthreads();
            // stage h[t][4 batches][128] as fp32 = hi + lo
            for (int i = tid; i < 4*Hn/2; i += NTHR){      // 256 pairs of units
                int bb = i >> 6;                           // 0..3
                int uu = (i & 63) * 2;
                size_t ho = (((size_t)7*Tn + t)*Bn + (og4*4 + bb))*Hn + uu;
                unsigned hp = *(const unsigned*)&g_hh[0][ho];
                unsigned lp = *(const unsigned*)&g_hh[1][ho];
                float h0 = __bfloat162float(__ushort_as_bfloat16((unsigned short)(hp & 0xFFFF)))
                         + __bfloat162float(__ushort_as_bfloat16((unsigned short)(lp & 0xFFFF)));
                float h1 = __bfloat162float(__ushort_as_bfloat16((unsigned short)(hp >> 16)))
                         + __bfloat162float(__ushort_as_bfloat16((unsigned short)(lp >> 16)));
                Hsm[bb*Hn + uu]     = h0;
                Hsm[bb*Hn + uu + 1] = h1;
            }
            __syncthreads();
            // FULL coverage: 260 work items on 256 threads (strided loop)
            for (int w = tid; w < 4*On; w += NTHR){
                int b4 = w / On;
                int oo = w - b4*On;
                const float* hr = &Hsm[b4*Hn];
                float acc = Bo[oo];
#pragma unroll 8
                for (int k = 0; k < Hn; ++k) acc += hr[k] * Wo[k*On + oo];
                out[((og4*4 + b4)*Tn + t)*On + oo] = acc;
            }
            __syncthreads();   // Hsm reuse safe
        }
        return;
    }

    // =========================== LAYER CTAs ===============================
    float* Gsm = (float*)(smraw + SM_GSM);                 // [64][LDG]
    float* Bsm = (float*)(smraw + SM_BIAS);                // [32]
    __nv_bfloat16* Ahi = (__nv_bfloat16*)(smraw + SM_AHI); // [64][LDA]
    __nv_bfloat16* Alo = (__nv_bfloat16*)(smraw + SM_ALO);
    __nv_bfloat16* Whi = (__nv_bfloat16*)(smraw + SM_WHI); // [32][LDA]
    __nv_bfloat16* Wlo = (__nv_bfloat16*)(smraw + SM_WLO);
    const unsigned sAhi = smaddr(Ahi), sAlo = smaddr(Alo);
    const unsigned sWhi = smaddr(Whi), sWlo = smaddr(Wlo);

    const int layer = blockIdx.x >> 4;
    const int gidx  = blockIdx.x & 15;
    const int wid   = tid >> 5;
    const int lane  = tid & 31;

    if (tid < 32) Bsm[tid] = g_bias[layer*G4 + gidx*32 + tid];

    // ---- stage W (once)
    {
        const char* ws[2] = { (const char*)&g_W[0][((layer*CPL+gidx)*32)*256],
                              (const char*)&g_W[1][((layer*CPL+gidx)*32)*256] };
#pragma unroll
        for (int j = 0; j < 8; ++j){
            int id = j*NTHR + tid, arr = id>>10, rem = id&1023;
            int n = rem>>5, k0 = (rem&31)*8;
            cpa16((arr ? sWlo : sWhi) + (unsigned)(n*LDA + k0)*2u, ws[arr] + (n*256 + k0)*2);
        }
        cpa_commit();
        cpa_wait0();
    }
    __syncthreads();

    // wmma tile: rows [r16, r16+16), cols [c16, c16+16)
    const int r16 = (wid >> 1) * 16;
    const int c16 = (wid & 1)  * 16;
    // per-warp cell mapping: lane -> batch cb, 2 units starting at ug0
    const int cb  = r16 + (lane >> 1);
    const int cs  = lane & 1;
    const int ug0 = gidx*8 + (wid & 1)*4 + cs*2;

    float bia[8];
#pragma unroll
    for (int j = 0; j < 8; ++j) bia[j] = Bsm[c16 + cs*8 + j];

    float cst0 = 0.f, cst1 = 0.f;

    unsigned* cnt_own   = &g_cnt[layer*Tn];
    unsigned* cnt_below = (layer > 0) ? &g_cnt[(layer-1)*Tn] : nullptr;

    for (int t = 0; t < Tn; ++t){
        // ---- per-warp poll (lanes 0/1), no CTA barrier ----
        if (lane == 0 && layer > 0){ while (ld_acq(&cnt_below[t]) < CPL) __nanosleep(8); }
        if (lane == 1 && t > 0)    { while (ld_acq(&cnt_own[t-1]) < CPL) __nanosleep(8); }
        __syncwarp();

        // ---- split-group staging: group A = below half (k<128) ----
        {
            const char* h0b[2];
            if (layer > 0){
                h0b[0] = (const char*)&g_hh[0][((size_t)(layer-1)*Tn + t)*Bn*Hn];
                h0b[1] = (const char*)&g_hh[1][((size_t)(layer-1)*Tn + t)*Bn*Hn];
            } else { h0b[0] = (const char*)g_emb[0]; h0b[1] = (const char*)g_emb[1]; }
            const int* xr = &g_xT[t*Bn];
#pragma unroll
            for (int j = 0; j < 8; ++j){
                int id = j*NTHR + tid, arr = id>>10, rem = id&1023;
                int b = rem>>4, kc = rem&15, k0 = kc*8;
                unsigned dst = (arr ? sAlo : sAhi) + (unsigned)(b*LDA + k0)*2u;
                const char* s = (layer==0) ? h0b[arr] + (xr[b]*Hn + k0)*2
                                           : h0b[arr] + (b*Hn + k0)*2;
                cpa16(dst, s);
            }
            cpa_commit();
        }
        // ---- group B = own half (k>=128) ----
        {
            const char* h1b[2];
            if (t > 0){
                h1b[0] = (const char*)&g_hh[0][((size_t)layer*Tn + (t-1))*Bn*Hn];
                h1b[1] = (const char*)&g_hh[1][((size_t)layer*Tn + (t-1))*Bn*Hn];
            }
#pragma unroll
            for (int j = 0; j < 8; ++j){
                int id = j*NTHR + tid, arr = id>>10, rem = id&1023;
                int b = rem>>4, kc = rem&15, k0 = 128 + kc*8;
                unsigned dst = (arr ? sAlo : sAhi) + (unsigned)(b*LDA + k0)*2u;
                if (t > 0) cpa16(dst, h1b[arr] + (b*Hn + kc*8)*2);
                else       sts_zero16(dst);
            }
            cpa_commit();
        }

        cpa_wait1();       // group A complete
        __syncthreads();   // barrier 1: below half visible to all warps

        // ---- MMA on below half (ks 0..7) while own half drains ----
        wmma::fragment<wmma::accumulator, 16,16,16, float> acc;
        wmma::fill_fragment(acc, 0.0f);
#pragma unroll
        for (int ks = 0; ks < 8; ++ks){
            wmma::fragment<wmma::matrix_a, 16,16,16, __nv_bfloat16, wmma::row_major> ah, al;
            wmma::fragment<wmma::matrix_b, 16,16,16, __nv_bfloat16, wmma::col_major> bh, bl;
            wmma::load_matrix_sync(ah, Ahi + r16*LDA + ks*16, LDA);
            wmma::load_matrix_sync(al, Alo + r16*LDA + ks*16, LDA);
            wmma::load_matrix_sync(bh, Whi + c16*LDA + ks*16, LDA);
            wmma::load_matrix_sync(bl, Wlo + c16*LDA + ks*16, LDA);
            wmma::mma_sync(acc, ah, bh, acc);
            wmma::mma_sync(acc, ah, bl, acc);
            wmma::mma_sync(acc, al, bh, acc);
        }

        cpa_wait0();       // group B complete
        __syncthreads();   // barrier 2: own half visible to all warps

        // ---- MMA on own half (ks 8..15) ----
#pragma unroll
        for (int ks = 8; ks < 16; ++ks){
            wmma::fragment<wmma::matrix_a, 16,16,16, __nv_bfloat16, wmma::row_major> ah, al;
            wmma::fragment<wmma::matrix_b, 16,16,16, __nv_bfloat16, wmma::col_major> bh, bl;
            wmma::load_matrix_sync(ah, Ahi + r16*LDA + ks*16, LDA);
            wmma::load_matrix_sync(al, Alo + r16*LDA + ks*16, LDA);
            wmma::load_matrix_sync(bh, Whi + c16*LDA + ks*16, LDA);
            wmma::load_matrix_sync(bl, Wlo + c16*LDA + ks*16, LDA);
            wmma::mma_sync(acc, ah, bh, acc);
            wmma::mma_sync(acc, ah, bl, acc);
            wmma::mma_sync(acc, al, bh, acc);
        }
        wmma::store_matrix_sync(&Gsm[r16*LDG + c16], acc, LDG, wmma::mem_row_major);
        __syncwarp();      // warp-private Gsm tile visible within warp

        // ---- per-warp cell: 2 cells per lane ----
        {
            const float* gr = &Gsm[cb*LDG + c16 + cs*8];
            float4 gA = *(const float4*)(gr);        // unit ug0:   i f g o
            float4 gB = *(const float4*)(gr + 4);    // unit ug0+1: i f g o
            float i0 = fsig (gA.x + bia[0]);
            float f0 = fsig (gA.y + bia[1]);
            float g0 = ftanh(gA.z + bia[2]);
            float o0 = fsig (gA.w + bia[3]);
            float i1 = fsig (gB.x + bia[4]);
            float f1 = fsig (gB.y + bia[5]);
            float g1 = ftanh(gB.z + bia[6]);
            float o1 = fsig (gB.w + bia[7]);
            cst0 = f0*cst0 + i0*g0;
            cst1 = f1*cst1 + i1*g1;
            float h0 = o0 * ftanh(cst0);
            float h1 = o1 * ftanh(cst1);

            __nv_bfloat16 bh0 = __float2bfloat16_rn(h0);
            __nv_bfloat16 bh1 = __float2bfloat16_rn(h1);
            __nv_bfloat16 bl0 = __float2bfloat16_rn(h0 - __bfloat162float(bh0));
            __nv_bfloat16 bl1 = __float2bfloat16_rn(h1 - __bfloat162float(bh1));
            unsigned hp = ((unsigned)__bfloat16_as_ushort(bh1)<<16) | __bfloat16_as_ushort(bh0);
            unsigned lp = ((unsigned)__bfloat16_as_ushort(bl1)<<16) | __bfloat16_as_ushort(bl0);

            size_t ho = (((size_t)layer*Tn + t)*Bn + cb)*Hn + ug0;
            *(unsigned*)&g_hh[0][ho] = hp;
            *(unsigned*)&g_hh[1][ho] = lp;
            if (t == Tn-1){
                *(float2*)&out[OUT_H_BASE + (layer*Bn + cb)*Hn + ug0] = make_float2(h0, h1);
                *(float2*)&out[OUT_C_BASE + (layer*Bn + cb)*Hn + ug0] = make_float2(cst0, cst1);
            }
        }

        // ---- barrier 3: MMA reads + h-stores done; then single release ----
        __syncthreads();
        if (tid == 0) red_rel_add(&cnt_own[t]);
    }
}

// ---------------------------------------------------------------------------
extern "C" void kernel_launch(void* const* d_in, const int* in_sizes, int n_in,
                              void* d_out, int out_size)
{
    const int*   x     = (const int*)  d_in[0];
    const float* embed = (const float*)d_in[1];
    const float* w_ih  = (const float*)d_in[2];
    const float* b_ih  = (const float*)d_in[3];
    const float* w_hh  = (const float*)d_in[4];
    const float* b_hh  = (const float*)d_in[5];
    const float* w_out = (const float*)d_in[6];
    const float* b_out = (const float*)d_in[7];
    float* out = (float*)d_out;

    size_t smem_lstm = SM_TOTAL;                                   // 110,848 B
    cudaFuncSetAttribute(k_lstm, cudaFuncAttributeMaxDynamicSharedMemorySize, (int)smem_lstm);

    k_reset<<<128, 256>>>(x);
    k_prep_w<<<(Ln*G4*256)/256, 256>>>(w_ih, w_hh, b_ih, b_hh);
    k_prep_e<<<(Vn*Hn + 255)/256, 256>>>(embed);
    k_lstm<<<Ln*CPL + 16, NTHR, smem_lstm>>>(out, w_out, b_out);
}